// round 1
// baseline (speedup 1.0000x reference)
#include <cuda_runtime.h>
#include <math.h>

#define NB 4096
#define IN_DIM 1024
#define HID 512
#define EMBED 128
#define NTOK 16
#define NCODES 1024
#define LATENT 2048          // EMBED * NTOK
#define NTOKENS_TOTAL (NB * NTOK)          // 65536
#define QELEMS (NTOKENS_TOTAL * EMBED)     // 8388608
#define REC_ELEMS (NB * IN_DIM)            // 4194304

// ------------------------- scratch (static device globals) -------------------------
__device__ float  g_h1[NB * HID];
__device__ float  g_h2[NB * HID];
__device__ float  g_z [NB * LATENT];
__device__ float  g_q [NB * LATENT];
__device__ float  g_h3[NB * HID];
__device__ float  g_h4[NB * HID];
__device__ float  g_cnorm[NCODES];
__device__ int    g_idx[NTOKENS_TOTAL];
__device__ double g_loss;

// ------------------------- helpers -------------------------
__device__ __forceinline__ float gelu_exact(float x) {
    return 0.5f * x * (1.0f + erff(x * 0.70710678118654752440f));
}

// ------------------------- generic fp32 GEMM: C = act(A@W + b) -------------------------
// A: [M,K] row-major, W: [K,N] row-major, bias: [N]
// 64x64 block tile, 16x16 threads, 4x4 micro-tile, K-tile 16.
// Requires M%64==0, N%64==0, K%16==0 (true for all shapes here).
template <int ACT>
__global__ __launch_bounds__(256)
void gemm_bias_act(const float* __restrict__ A, const float* __restrict__ W,
                   const float* __restrict__ bias, float* __restrict__ C,
                   int M, int K, int N)
{
    __shared__ float As[16][65];  // [k][m]
    __shared__ float Bs[16][65];  // [k][n]
    const int tx = threadIdx.x, ty = threadIdx.y;
    const int tid = ty * 16 + tx;
    const int m0 = blockIdx.y * 64;
    const int n0 = blockIdx.x * 64;

    float acc[4][4] = {};

    for (int k0 = 0; k0 < K; k0 += 16) {
        #pragma unroll
        for (int l = 0; l < 4; l++) {
            int e = tid + l * 256;
            int row = e >> 4, col = e & 15;               // row: m-in-tile, col: k-in-tile
            As[col][row] = A[(size_t)(m0 + row) * K + k0 + col];
        }
        #pragma unroll
        for (int l = 0; l < 4; l++) {
            int e = tid + l * 256;
            int row = e >> 6, col = e & 63;               // row: k-in-tile, col: n-in-tile
            Bs[row][col] = W[(size_t)(k0 + row) * N + n0 + col];
        }
        __syncthreads();
        #pragma unroll
        for (int kk = 0; kk < 16; kk++) {
            float a[4], b[4];
            #pragma unroll
            for (int i = 0; i < 4; i++) a[i] = As[kk][ty + 16 * i];
            #pragma unroll
            for (int j = 0; j < 4; j++) b[j] = Bs[kk][tx + 16 * j];
            #pragma unroll
            for (int i = 0; i < 4; i++)
                #pragma unroll
                for (int j = 0; j < 4; j++)
                    acc[i][j] = fmaf(a[i], b[j], acc[i][j]);
        }
        __syncthreads();
    }

    #pragma unroll
    for (int i = 0; i < 4; i++) {
        int m = m0 + ty + 16 * i;
        #pragma unroll
        for (int j = 0; j < 4; j++) {
            int n = n0 + tx + 16 * j;
            float v = acc[i][j] + bias[n];
            if (ACT) v = gelu_exact(v);
            C[(size_t)m * N + n] = v;
        }
    }
}

// ------------------------- codebook row norms -------------------------
__global__ void code_norm_kernel(const float* __restrict__ cb) {
    int c = blockIdx.x * blockDim.x + threadIdx.x;
    if (c < NCODES) {
        float s = 0.f;
        #pragma unroll 4
        for (int d = 0; d < EMBED; d++) {
            float v = cb[c * EMBED + d];
            s = fmaf(v, v, s);
        }
        g_cnorm[c] = s;
    }
}

__global__ void zero_loss_kernel() { g_loss = 0.0; }

// ------------------------- VQ argmin -------------------------
// Each block: 64 tokens, all 1024 codes in chunks of 64, K=128 dot products.
// dist = cnorm[c] - 2 * (z . cb[c]); first-min tie-break matches jnp.argmin.
__global__ __launch_bounds__(256)
void vq_argmin_kernel(const float* __restrict__ z, const float* __restrict__ cb)
{
    __shared__ float Zs[128][65];  // [k][token] : full z tile (64 tokens x 128 dims)
    __shared__ float Cs[16][65];   // [k][code]
    __shared__ float sd[64][16];
    __shared__ int   si[64][16];

    const int tx = threadIdx.x, ty = threadIdx.y;
    const int tid = ty * 16 + tx;
    const int t0 = blockIdx.x * 64;

    // load z tile once (8192 elements, 32/thread, coalesced)
    #pragma unroll
    for (int l = 0; l < 32; l++) {
        int e = tid + l * 256;
        int col = e & 127;     // k
        int row = e >> 7;      // token
        Zs[col][row] = z[(size_t)(t0 + row) * EMBED + col];
    }
    __syncthreads();

    float bestD[4];
    int   bestI[4];
    #pragma unroll
    for (int i = 0; i < 4; i++) { bestD[i] = 3.4e38f; bestI[i] = 0; }

    for (int c0 = 0; c0 < NCODES; c0 += 64) {
        float acc[4][4] = {};
        for (int k0 = 0; k0 < EMBED; k0 += 16) {
            __syncthreads();
            #pragma unroll
            for (int l = 0; l < 4; l++) {
                int e = tid + l * 256;
                int kk = e & 15, code = e >> 4;
                Cs[kk][code] = cb[(size_t)(c0 + code) * EMBED + k0 + kk];
            }
            __syncthreads();
            #pragma unroll
            for (int kk = 0; kk < 16; kk++) {
                float a[4], b[4];
                #pragma unroll
                for (int i = 0; i < 4; i++) a[i] = Zs[k0 + kk][ty + 16 * i];
                #pragma unroll
                for (int j = 0; j < 4; j++) b[j] = Cs[kk][tx + 16 * j];
                #pragma unroll
                for (int i = 0; i < 4; i++)
                    #pragma unroll
                    for (int j = 0; j < 4; j++)
                        acc[i][j] = fmaf(a[i], b[j], acc[i][j]);
            }
        }
        // update running argmin (codes scanned in increasing index per thread)
        #pragma unroll
        for (int j = 0; j < 4; j++) {
            int c = c0 + tx + 16 * j;
            float cn = g_cnorm[c];
            #pragma unroll
            for (int i = 0; i < 4; i++) {
                float d = cn - 2.0f * acc[i][j];
                if (d < bestD[i]) { bestD[i] = d; bestI[i] = c; }
            }
        }
    }

    // cross-thread reduction per token (16 tx lanes per token row)
    #pragma unroll
    for (int i = 0; i < 4; i++) {
        sd[ty + 16 * i][tx] = bestD[i];
        si[ty + 16 * i][tx] = bestI[i];
    }
    __syncthreads();
    if (tid < 64) {
        float bd = sd[tid][0];
        int   bi = si[tid][0];
        #pragma unroll
        for (int x = 1; x < 16; x++) {
            float d = sd[tid][x];
            int   c = si[tid][x];
            if (d < bd || (d == bd && c < bi)) { bd = d; bi = c; }
        }
        g_idx[t0 + tid] = bi;
    }
}

// ------------------------- gather + straight-through + commit loss -------------------------
__global__ __launch_bounds__(256)
void gather_loss_kernel(const float* __restrict__ z, const float* __restrict__ cb)
{
    int e = blockIdx.x * 256 + threadIdx.x;    // e < QELEMS (exact multiple)
    int t = e >> 7;
    int d = e & 127;
    int c = g_idx[t];
    float zv = z[e];
    float diff = cb[(size_t)c * EMBED + d] - zv;   // quantized - z
    g_q[e] = zv + diff;                            // straight-through, same rounding as jax
    float sq = diff * diff;

    // block reduce -> atomicAdd(double)
    #pragma unroll
    for (int o = 16; o > 0; o >>= 1) sq += __shfl_down_sync(0xFFFFFFFFu, sq, o);
    __shared__ float ws[8];
    int lane = threadIdx.x & 31, wid = threadIdx.x >> 5;
    if (lane == 0) ws[wid] = sq;
    __syncthreads();
    if (threadIdx.x == 0) {
        float s = 0.f;
        #pragma unroll
        for (int w = 0; w < 8; w++) s += ws[w];
        atomicAdd(&g_loss, (double)s);
    }
}

// ------------------------- tail outputs: indices (as float) + loss -------------------------
__global__ void finalize_kernel(float* __restrict__ out)
{
    int i = blockIdx.x * 256 + threadIdx.x;
    if (i < NTOKENS_TOTAL) out[REC_ELEMS + i] = (float)g_idx[i];
    if (i == 0) out[REC_ELEMS + NTOKENS_TOTAL] = (float)(g_loss / (double)QELEMS);
}

// ------------------------- launch -------------------------
extern "C" void kernel_launch(void* const* d_in, const int* in_sizes, int n_in,
                              void* d_out, int out_size)
{
    const float* x   = (const float*)d_in[0];
    const float* eW1 = (const float*)d_in[1];
    const float* eb1 = (const float*)d_in[2];
    const float* eW2 = (const float*)d_in[3];
    const float* eb2 = (const float*)d_in[4];
    const float* eW3 = (const float*)d_in[5];
    const float* eb3 = (const float*)d_in[6];
    const float* dW1 = (const float*)d_in[7];
    const float* db1 = (const float*)d_in[8];
    const float* dW2 = (const float*)d_in[9];
    const float* db2 = (const float*)d_in[10];
    const float* dW3 = (const float*)d_in[11];
    const float* db3 = (const float*)d_in[12];
    const float* cb  = (const float*)d_in[13];
    float* out = (float*)d_out;

    float *h1, *h2, *z, *q, *h3, *h4;
    cudaGetSymbolAddress((void**)&h1, g_h1);
    cudaGetSymbolAddress((void**)&h2, g_h2);
    cudaGetSymbolAddress((void**)&z,  g_z);
    cudaGetSymbolAddress((void**)&q,  g_q);
    cudaGetSymbolAddress((void**)&h3, g_h3);
    cudaGetSymbolAddress((void**)&h4, g_h4);

    dim3 blk(16, 16);

    zero_loss_kernel<<<1, 1>>>();
    code_norm_kernel<<<4, 256>>>(cb);

    // encoder
    gemm_bias_act<1><<<dim3(HID / 64,   NB / 64), blk>>>(x,  eW1, eb1, h1, NB, IN_DIM, HID);
    gemm_bias_act<1><<<dim3(HID / 64,   NB / 64), blk>>>(h1, eW2, eb2, h2, NB, HID,    HID);
    gemm_bias_act<0><<<dim3(LATENT / 64, NB / 64), blk>>>(h2, eW3, eb3, z,  NB, HID,    LATENT);

    // VQ
    vq_argmin_kernel<<<NTOKENS_TOTAL / 64, blk>>>(z, cb);
    gather_loss_kernel<<<QELEMS / 256, 256>>>(z, cb);

    // decoder
    gemm_bias_act<1><<<dim3(HID / 64,   NB / 64), blk>>>(q,  dW1, db1, h3, NB, LATENT, HID);
    gemm_bias_act<1><<<dim3(HID / 64,   NB / 64), blk>>>(h3, dW2, db2, h4, NB, HID,    HID);
    gemm_bias_act<0><<<dim3(IN_DIM / 64, NB / 64), blk>>>(h4, dW3, db3, out, NB, HID,   IN_DIM);

    // indices + commit loss, if the output buffer includes them
    if (out_size >= REC_ELEMS + NTOKENS_TOTAL + 1)
        finalize_kernel<<<(NTOKENS_TOTAL + 255) / 256, 256>>>(out);
}

// round 2
// speedup vs baseline: 1.3115x; 1.3115x over previous
#include <cuda_runtime.h>
#include <math.h>

#define NB 4096
#define IN_DIM 1024
#define HID 512
#define EMBED 128
#define NTOK 16
#define NCODES 1024
#define LATENT 2048
#define NTOKENS_TOTAL (NB * NTOK)          // 65536
#define QELEMS (NTOKENS_TOTAL * EMBED)     // 8388608
#define REC_ELEMS (NB * IN_DIM)            // 4194304

// ------------------------- scratch -------------------------
__device__ float  g_h1[NB * HID];
__device__ float  g_h2[NB * HID];
__device__ float  g_z [NB * LATENT];
__device__ float  g_q [NB * LATENT];
__device__ float  g_h3[NB * HID];
__device__ float  g_h4[NB * HID];
__device__ float  g_cnorm[NCODES];
__device__ int    g_idx[NTOKENS_TOTAL];
__device__ double g_loss;

__device__ __forceinline__ float gelu_exact(float x) {
    return 0.5f * x * (1.0f + erff(x * 0.70710678118654752440f));
}

// =========================================================================
// fp32 GEMM: C = act(A@W + b)
// A [M,K] rm, W [K,N] rm. 128x128 tile, BK=8, 256 threads, 8x8 micro-tile.
// Requires M%128==0, N%128==0, K%8==0.
// =========================================================================
template <int ACT>
__global__ __launch_bounds__(256)
void gemm128(const float* __restrict__ A, const float* __restrict__ W,
             const float* __restrict__ bias, float* __restrict__ C,
             int M, int K, int N)
{
    __shared__ __align__(16) float As[2][8][132];   // [k][m]
    __shared__ __align__(16) float Ws[2][8][128];   // [k][n]

    const int tid  = threadIdx.x;
    const int m0   = blockIdx.y * 128;
    const int n0   = blockIdx.x * 128;

    // global load mapping
    const int arow = tid >> 1;              // 0..127 (m in tile)
    const int akq  = (tid & 1) * 4;         // k quad
    const int wrow = tid >> 5;              // 0..7 (k in tile)
    const int wcol = (tid & 31) * 4;        // 0..124 (n in tile)
    const float* Aptr = A + (size_t)(m0 + arow) * K + akq;
    const float* Wptr = W + (size_t)wrow * N + n0 + wcol;

    // compute mapping
    const int warp = tid >> 5, lane = tid & 31;
    const int wm = warp & 3, wn = warp >> 2;
    const int lm = lane & 3, ln = lane >> 2;
    const int ma = wm * 32 + lm * 4;        // + {0..3}, +16..
    const int nb = wn * 64 + ln * 4;        // + {0..3}, +32..

    float4 av = *(const float4*)Aptr;
    float4 wv = *(const float4*)Wptr;
    As[0][akq + 0][arow] = av.x;
    As[0][akq + 1][arow] = av.y;
    As[0][akq + 2][arow] = av.z;
    As[0][akq + 3][arow] = av.w;
    *(float4*)&Ws[0][wrow][wcol] = wv;
    __syncthreads();

    float acc[8][8] = {};
    const int KT = K >> 3;

    for (int kt = 0; kt < KT; kt++) {
        const int cur = kt & 1, nxt = cur ^ 1;
        if (kt + 1 < KT) {
            av = *(const float4*)(Aptr + (kt + 1) * 8);
            wv = *(const float4*)(Wptr + (size_t)(kt + 1) * 8 * N);
        }
        #pragma unroll
        for (int k = 0; k < 8; k++) {
            float4 a0 = *(const float4*)&As[cur][k][ma];
            float4 a1 = *(const float4*)&As[cur][k][ma + 16];
            float4 b0 = *(const float4*)&Ws[cur][k][nb];
            float4 b1 = *(const float4*)&Ws[cur][k][nb + 32];
            float a[8] = {a0.x, a0.y, a0.z, a0.w, a1.x, a1.y, a1.z, a1.w};
            float b[8] = {b0.x, b0.y, b0.z, b0.w, b1.x, b1.y, b1.z, b1.w};
            #pragma unroll
            for (int i = 0; i < 8; i++)
                #pragma unroll
                for (int j = 0; j < 8; j++)
                    acc[i][j] = fmaf(a[i], b[j], acc[i][j]);
        }
        if (kt + 1 < KT) {
            As[nxt][akq + 0][arow] = av.x;
            As[nxt][akq + 1][arow] = av.y;
            As[nxt][akq + 2][arow] = av.z;
            As[nxt][akq + 3][arow] = av.w;
            *(float4*)&Ws[nxt][wrow][wcol] = wv;
            __syncthreads();
        }
    }

    // epilogue: bias + act, float4 stores
    float4 bia0 = *(const float4*)&bias[n0 + nb];
    float4 bia1 = *(const float4*)&bias[n0 + nb + 32];
    float bj[8] = {bia0.x, bia0.y, bia0.z, bia0.w, bia1.x, bia1.y, bia1.z, bia1.w};
    #pragma unroll
    for (int i = 0; i < 8; i++) {
        int mr = m0 + ma + (i & 3) + ((i >> 2) * 16);
        #pragma unroll
        for (int jg = 0; jg < 2; jg++) {
            float4 v;
            float* vp = &v.x;
            #pragma unroll
            for (int q = 0; q < 4; q++) {
                float t = acc[i][jg * 4 + q] + bj[jg * 4 + q];
                if (ACT) t = gelu_exact(t);
                vp[q] = t;
            }
            *(float4*)&C[(size_t)mr * N + n0 + nb + jg * 32] = v;
        }
    }
}

// =========================================================================
// codebook norms
// =========================================================================
__global__ void code_norm_kernel(const float* __restrict__ cb) {
    int c = blockIdx.x * blockDim.x + threadIdx.x;
    if (c < NCODES) {
        float s = 0.f;
        #pragma unroll 4
        for (int d = 0; d < EMBED; d++) {
            float v = cb[c * EMBED + d];
            s = fmaf(v, v, s);
        }
        g_cnorm[c] = s;
    }
}

__global__ void zero_loss_kernel() { g_loss = 0.0; }

// =========================================================================
// VQ: 128 tokens/block x 1024 codes (8 c-tiles of 128), K=128.
// GEMM inner loop identical to gemm128; epilogue = argmin + gather + loss.
// =========================================================================
__global__ __launch_bounds__(256)
void vq_kernel(const float* __restrict__ z, const float* __restrict__ cb,
               float* __restrict__ q)
{
    __shared__ __align__(16) float Zs[2][8][132];   // [k][token]
    __shared__ __align__(16) float Cs[2][8][132];   // [k][code]
    __shared__ __align__(16) float cnorm_s[NCODES];
    __shared__ float red_d[128][16];
    __shared__ int   red_i[128][16];
    __shared__ int   best_idx[128];
    __shared__ float warp_sum[8];

    const int tid = threadIdx.x;
    const int t0  = blockIdx.x * 128;

    // cache code norms
    *(float4*)&cnorm_s[tid * 4] = *(const float4*)&g_cnorm[tid * 4];

    const int arow = tid >> 1;
    const int akq  = (tid & 1) * 4;
    const float* Zptr = z + (size_t)(t0 + arow) * EMBED + akq;

    const int warp = tid >> 5, lane = tid & 31;
    const int wm = warp & 3, wn = warp >> 2;
    const int lm = lane & 3, ln = lane >> 2;
    const int ma = wm * 32 + lm * 4;
    const int nb = wn * 64 + ln * 4;

    float bestD[8];
    int   bestI[8];
    #pragma unroll
    for (int i = 0; i < 8; i++) { bestD[i] = 3.4e38f; bestI[i] = 0; }

    const int KT = EMBED >> 3;  // 16

    for (int c0 = 0; c0 < NCODES; c0 += 128) {
        const float* Cptr = cb + (size_t)(c0 + arow) * EMBED + akq;

        float4 av = *(const float4*)Zptr;
        float4 cv = *(const float4*)Cptr;
        Zs[0][akq + 0][arow] = av.x;
        Zs[0][akq + 1][arow] = av.y;
        Zs[0][akq + 2][arow] = av.z;
        Zs[0][akq + 3][arow] = av.w;
        Cs[0][akq + 0][arow] = cv.x;
        Cs[0][akq + 1][arow] = cv.y;
        Cs[0][akq + 2][arow] = cv.z;
        Cs[0][akq + 3][arow] = cv.w;
        __syncthreads();

        float acc[8][8] = {};
        for (int kt = 0; kt < KT; kt++) {
            const int cur = kt & 1, nxt = cur ^ 1;
            if (kt + 1 < KT) {
                av = *(const float4*)(Zptr + (kt + 1) * 8);
                cv = *(const float4*)(Cptr + (kt + 1) * 8);
            }
            #pragma unroll
            for (int k = 0; k < 8; k++) {
                float4 a0 = *(const float4*)&Zs[cur][k][ma];
                float4 a1 = *(const float4*)&Zs[cur][k][ma + 16];
                float4 b0 = *(const float4*)&Cs[cur][k][nb];
                float4 b1 = *(const float4*)&Cs[cur][k][nb + 32];
                float a[8] = {a0.x, a0.y, a0.z, a0.w, a1.x, a1.y, a1.z, a1.w};
                float b[8] = {b0.x, b0.y, b0.z, b0.w, b1.x, b1.y, b1.z, b1.w};
                #pragma unroll
                for (int i = 0; i < 8; i++)
                    #pragma unroll
                    for (int j = 0; j < 8; j++)
                        acc[i][j] = fmaf(a[i], b[j], acc[i][j]);
            }
            if (kt + 1 < KT) {
                Zs[nxt][akq + 0][arow] = av.x;
                Zs[nxt][akq + 1][arow] = av.y;
                Zs[nxt][akq + 2][arow] = av.z;
                Zs[nxt][akq + 3][arow] = av.w;
                Cs[nxt][akq + 0][arow] = cv.x;
                Cs[nxt][akq + 1][arow] = cv.y;
                Cs[nxt][akq + 2][arow] = cv.z;
                Cs[nxt][akq + 3][arow] = cv.w;
                __syncthreads();
            }
        }

        // argmin update; j ascending -> code index ascending within thread
        #pragma unroll
        for (int j = 0; j < 8; j++) {
            int c = c0 + nb + (j & 3) + ((j >> 2) * 32);
            float cn = cnorm_s[c];
            #pragma unroll
            for (int i = 0; i < 8; i++) {
                float d = fmaf(-2.0f, acc[i][j], cn);
                if (d < bestD[i]) { bestD[i] = d; bestI[i] = c; }
            }
        }
        __syncthreads();   // protect smem reuse at next c-tile stage-0 fill
    }

    // per-token reduction across the 16 threads sharing each token row
    const int rcol = wn * 8 + ln;
    #pragma unroll
    for (int i = 0; i < 8; i++) {
        int tr = ma + (i & 3) + ((i >> 2) * 16);
        red_d[tr][rcol] = bestD[i];
        red_i[tr][rcol] = bestI[i];
    }
    __syncthreads();
    if (tid < 128) {
        float bd = red_d[tid][0];
        int   bi = red_i[tid][0];
        #pragma unroll
        for (int x = 1; x < 16; x++) {
            float d = red_d[tid][x];
            int   c = red_i[tid][x];
            if (d < bd || (d == bd && c < bi)) { bd = d; bi = c; }
        }
        best_idx[tid] = bi;
        g_idx[t0 + tid] = bi;
    }
    __syncthreads();

    // fused gather + straight-through + commit loss (16384 elems, 64/thread)
    float lsum = 0.f;
    const float* zB = z + (size_t)t0 * EMBED;
    float*       qB = q + (size_t)t0 * EMBED;
    #pragma unroll 4
    for (int l = 0; l < 64; l++) {
        int e = l * 256 + tid;
        int trow = e >> 7;
        int d    = e & 127;
        int c    = best_idx[trow];
        float zv   = zB[e];
        float diff = cb[(size_t)c * EMBED + d] - zv;
        qB[e] = zv + diff;
        lsum = fmaf(diff, diff, lsum);
    }
    #pragma unroll
    for (int o = 16; o > 0; o >>= 1) lsum += __shfl_down_sync(0xFFFFFFFFu, lsum, o);
    if (lane == 0) warp_sum[warp] = lsum;
    __syncthreads();
    if (tid == 0) {
        float s = 0.f;
        #pragma unroll
        for (int w = 0; w < 8; w++) s += warp_sum[w];
        atomicAdd(&g_loss, (double)s);
    }
}

// ------------------------- tail outputs -------------------------
__global__ void finalize_kernel(float* __restrict__ out)
{
    int i = blockIdx.x * 256 + threadIdx.x;
    if (i < NTOKENS_TOTAL) out[REC_ELEMS + i] = (float)g_idx[i];
    if (i == 0) out[REC_ELEMS + NTOKENS_TOTAL] = (float)(g_loss / (double)QELEMS);
}

// ------------------------- launch -------------------------
extern "C" void kernel_launch(void* const* d_in, const int* in_sizes, int n_in,
                              void* d_out, int out_size)
{
    const float* x   = (const float*)d_in[0];
    const float* eW1 = (const float*)d_in[1];
    const float* eb1 = (const float*)d_in[2];
    const float* eW2 = (const float*)d_in[3];
    const float* eb2 = (const float*)d_in[4];
    const float* eW3 = (const float*)d_in[5];
    const float* eb3 = (const float*)d_in[6];
    const float* dW1 = (const float*)d_in[7];
    const float* db1 = (const float*)d_in[8];
    const float* dW2 = (const float*)d_in[9];
    const float* db2 = (const float*)d_in[10];
    const float* dW3 = (const float*)d_in[11];
    const float* db3 = (const float*)d_in[12];
    const float* cb  = (const float*)d_in[13];
    float* out = (float*)d_out;

    float *h1, *h2, *z, *q, *h3, *h4;
    cudaGetSymbolAddress((void**)&h1, g_h1);
    cudaGetSymbolAddress((void**)&h2, g_h2);
    cudaGetSymbolAddress((void**)&z,  g_z);
    cudaGetSymbolAddress((void**)&q,  g_q);
    cudaGetSymbolAddress((void**)&h3, g_h3);
    cudaGetSymbolAddress((void**)&h4, g_h4);

    zero_loss_kernel<<<1, 1>>>();
    code_norm_kernel<<<4, 256>>>(cb);

    // encoder
    gemm128<1><<<dim3(HID / 128,    NB / 128), 256>>>(x,  eW1, eb1, h1, NB, IN_DIM, HID);
    gemm128<1><<<dim3(HID / 128,    NB / 128), 256>>>(h1, eW2, eb2, h2, NB, HID,    HID);
    gemm128<0><<<dim3(LATENT / 128, NB / 128), 256>>>(h2, eW3, eb3, z,  NB, HID,    LATENT);

    // VQ (argmin + gather + loss fused)
    vq_kernel<<<NTOKENS_TOTAL / 128, 256>>>(z, cb, q);

    // decoder
    gemm128<1><<<dim3(HID / 128,    NB / 128), 256>>>(q,  dW1, db1, h3, NB, LATENT, HID);
    gemm128<1><<<dim3(HID / 128,    NB / 128), 256>>>(h3, dW2, db2, h4, NB, HID,    HID);
    gemm128<0><<<dim3(IN_DIM / 128, NB / 128), 256>>>(h4, dW3, db3, out, NB, HID,   IN_DIM);

    if (out_size >= REC_ELEMS + NTOKENS_TOTAL + 1)
        finalize_kernel<<<(NTOKENS_TOTAL + 255) / 256, 256>>>(out);
}

// round 3
// speedup vs baseline: 1.8836x; 1.4362x over previous
#include <cuda_runtime.h>
#include <math.h>

#define NB 4096
#define IN_DIM 1024
#define HID 512
#define EMBED 128
#define NTOK 16
#define NCODES 1024
#define LATENT 2048
#define NTOKENS_TOTAL (NB * NTOK)          // 65536
#define QELEMS (NTOKENS_TOTAL * EMBED)     // 8388608
#define REC_ELEMS (NB * IN_DIM)            // 4194304

// ------------------------- scratch -------------------------
__device__ float  g_h1[NB * HID];
__device__ float  g_h2[NB * HID];
__device__ float  g_z [NB * LATENT];
__device__ float  g_q [NB * LATENT];
__device__ float  g_h3[NB * HID];
__device__ float  g_h4[NB * HID];
__device__ float  g_cnorm[NCODES];
__device__ int    g_idx[NTOKENS_TOTAL];
__device__ double g_loss;

__device__ __forceinline__ float gelu_exact(float x) {
    return 0.5f * x * (1.0f + erff(x * 0.70710678118654752440f));
}

// ------------------------- tf32 helpers -------------------------
__device__ __forceinline__ unsigned f2tf(float x) {
    unsigned u;
    asm("cvt.rna.tf32.f32 %0, %1;" : "=r"(u) : "f"(x));
    return u;
}
__device__ __forceinline__ void split_tf(float x, unsigned &hi, unsigned &lo) {
    hi = f2tf(x);
    lo = f2tf(x - __uint_as_float(hi));
}
__device__ __forceinline__ void mma8(float* d,
                                     unsigned a0, unsigned a1, unsigned a2, unsigned a3,
                                     unsigned b0, unsigned b1) {
    asm volatile(
        "mma.sync.aligned.m16n8k8.row.col.f32.tf32.tf32.f32 "
        "{%0,%1,%2,%3},{%4,%5,%6,%7},{%8,%9},{%0,%1,%2,%3};"
        : "+f"(d[0]), "+f"(d[1]), "+f"(d[2]), "+f"(d[3])
        : "r"(a0), "r"(a1), "r"(a2), "r"(a3), "r"(b0), "r"(b1));
}

// =========================================================================
// tensor-core GEMM: C = act(A@W + b), A [M,K] rm, W [K,N] rm
// 128x128 tile, BK=16, 256 threads (8 warps, 2x4), warp tile 64x32.
// 3xTF32 for fp32-level accuracy.
// =========================================================================
template <int ACT>
__global__ __launch_bounds__(256, 1)
void gemm_tc(const float* __restrict__ A, const float* __restrict__ W,
             const float* __restrict__ bias, float* __restrict__ C,
             int M, int K, int N)
{
    __shared__ __align__(16) float As[2][128][20];   // [m][k], pad->conflict-free
    __shared__ __align__(16) float Ws[2][16][136];   // [k][n]

    const int tid  = threadIdx.x;
    const int m0   = blockIdx.y * 128;
    const int n0   = blockIdx.x * 128;
    const int warp = tid >> 5, lane = tid & 31;
    const int warpM = warp & 1, warpN = warp >> 1;
    const int mw = warpM * 64;
    const int nw = warpN * 32;
    const int g  = lane >> 2;      // group id (0..7)
    const int tq = lane & 3;       // thread in group (0..3)

    // global load mapping
    const int am = tid >> 2;            // 0..63 (and +64)
    const int ak = (tid & 3) * 4;       // 0,4,8,12
    const int wk = tid >> 5;            // 0..7 (and +8)
    const int wn = (tid & 31) * 4;
    const float* Ap = A + (size_t)(m0 + am) * K + ak;
    const float* Wp = W + (size_t)wk * N + n0 + wn;

    float acc[4][4][4] = {};

    float4 a0v = *(const float4*)Ap;
    float4 a1v = *(const float4*)(Ap + (size_t)64 * K);
    float4 w0v = *(const float4*)Wp;
    float4 w1v = *(const float4*)(Wp + (size_t)8 * N);
    *(float4*)&As[0][am][ak]      = a0v;
    *(float4*)&As[0][am + 64][ak] = a1v;
    *(float4*)&Ws[0][wk][wn]      = w0v;
    *(float4*)&Ws[0][wk + 8][wn]  = w1v;
    __syncthreads();

    const int KT = K >> 4;
    for (int kt = 0; kt < KT; kt++) {
        const int cur = kt & 1, nxt = cur ^ 1;
        if (kt + 1 < KT) {
            a0v = *(const float4*)(Ap + (kt + 1) * 16);
            a1v = *(const float4*)(Ap + (size_t)64 * K + (kt + 1) * 16);
            w0v = *(const float4*)(Wp + (size_t)((kt + 1) * 16) * N);
            w1v = *(const float4*)(Wp + (size_t)((kt + 1) * 16 + 8) * N);
        }
        #pragma unroll
        for (int ks = 0; ks < 16; ks += 8) {
            unsigned ahi[4][4], alo[4][4];
            #pragma unroll
            for (int i = 0; i < 4; i++) {
                const int r0 = mw + i * 16 + g;
                split_tf(As[cur][r0][ks + tq],          ahi[i][0], alo[i][0]);
                split_tf(As[cur][r0 + 8][ks + tq],      ahi[i][1], alo[i][1]);
                split_tf(As[cur][r0][ks + tq + 4],      ahi[i][2], alo[i][2]);
                split_tf(As[cur][r0 + 8][ks + tq + 4],  ahi[i][3], alo[i][3]);
            }
            unsigned bhi[4][2], blo[4][2];
            #pragma unroll
            for (int j = 0; j < 4; j++) {
                const int nc = nw + j * 8 + g;
                split_tf(Ws[cur][ks + tq][nc],     bhi[j][0], blo[j][0]);
                split_tf(Ws[cur][ks + tq + 4][nc], bhi[j][1], blo[j][1]);
            }
            #pragma unroll
            for (int i = 0; i < 4; i++)
                #pragma unroll
                for (int j = 0; j < 4; j++) {
                    mma8(acc[i][j], ahi[i][0], ahi[i][1], ahi[i][2], ahi[i][3], bhi[j][0], bhi[j][1]);
                    mma8(acc[i][j], ahi[i][0], ahi[i][1], ahi[i][2], ahi[i][3], blo[j][0], blo[j][1]);
                    mma8(acc[i][j], alo[i][0], alo[i][1], alo[i][2], alo[i][3], bhi[j][0], bhi[j][1]);
                }
        }
        if (kt + 1 < KT) {
            *(float4*)&As[nxt][am][ak]      = a0v;
            *(float4*)&As[nxt][am + 64][ak] = a1v;
            *(float4*)&Ws[nxt][wk][wn]      = w0v;
            *(float4*)&Ws[nxt][wk + 8][wn]  = w1v;
            __syncthreads();
        }
    }

    // epilogue: bias + act
    #pragma unroll
    for (int j = 0; j < 4; j++) {
        const int col = n0 + nw + j * 8 + tq * 2;
        const float b0 = bias[col], b1 = bias[col + 1];
        #pragma unroll
        for (int i = 0; i < 4; i++) {
            const int r = m0 + mw + i * 16 + g;
            float v0 = acc[i][j][0] + b0;
            float v1 = acc[i][j][1] + b1;
            float v2 = acc[i][j][2] + b0;
            float v3 = acc[i][j][3] + b1;
            if (ACT) { v0 = gelu_exact(v0); v1 = gelu_exact(v1); v2 = gelu_exact(v2); v3 = gelu_exact(v3); }
            *(float2*)&C[(size_t)r * N + col]       = make_float2(v0, v1);
            *(float2*)&C[(size_t)(r + 8) * N + col] = make_float2(v2, v3);
        }
    }
}

// ------------------------- codebook norms -------------------------
__global__ void code_norm_kernel(const float* __restrict__ cb) {
    int c = blockIdx.x * blockDim.x + threadIdx.x;
    if (c < NCODES) {
        float s = 0.f;
        #pragma unroll 4
        for (int d = 0; d < EMBED; d++) {
            float v = cb[c * EMBED + d];
            s = fmaf(v, v, s);
        }
        g_cnorm[c] = s;
    }
}

__global__ void zero_loss_kernel() { g_loss = 0.0; }

// =========================================================================
// VQ: 128 tokens/block, 1024 codes (8 c-tiles), K=128, tensor-core distances.
// Full z tile resident in smem; fused argmin + gather + commit loss.
// =========================================================================
__global__ __launch_bounds__(256, 1)
void vq_kernel(const float* __restrict__ z, const float* __restrict__ cb,
               float* __restrict__ q)
{
    extern __shared__ float dsm[];
    float* Zs = dsm;                       // [128][132]  (m-major, k stride pad 132)
    float* Cs = Zs + 128 * 132;            // [2][128][20] (code-major, like As)
    float* cn = Cs + 2 * 128 * 20;         // [1024]

    __shared__ float red_d[128][4];
    __shared__ int   red_i[128][4];
    __shared__ int   best_idx[128];
    __shared__ float warp_sum[8];

    const int tid = threadIdx.x;
    const int t0  = blockIdx.x * 128;
    const int warp = tid >> 5, lane = tid & 31;
    const int warpM = warp & 1, warpN = warp >> 1;
    const int mw = warpM * 64;
    const int nw = warpN * 32;
    const int g  = lane >> 2;
    const int tq = lane & 3;

    // cnorm -> smem
    *(float4*)&cn[tid * 4] = *(const float4*)&g_cnorm[tid * 4];

    // z tile -> smem (4096 float4, 16/thread)
    #pragma unroll
    for (int l = 0; l < 16; l++) {
        int idx4 = l * 256 + tid;
        int m = idx4 >> 5;
        int k4 = (idx4 & 31) * 4;
        *(float4*)&Zs[m * 132 + k4] = *(const float4*)&z[(size_t)(t0 + m) * EMBED + k4];
    }

    // codebook tile loader mapping: 2 float4/thread/stage
    const int crow = tid >> 2;           // 0..63 (and +64)
    const int ckq  = (tid & 3) * 4;      // 0,4,8,12

    float bestD[8];
    int   bestI[8];
    #pragma unroll
    for (int s = 0; s < 8; s++) { bestD[s] = 3.4e38f; bestI[s] = 0; }

    for (int ct = 0; ct < 8; ct++) {
        const int c0 = ct * 128;
        const float* Cp0 = cb + (size_t)(c0 + crow) * EMBED + ckq;
        const float* Cp1 = cb + (size_t)(c0 + crow + 64) * EMBED + ckq;

        float4 c0v = *(const float4*)Cp0;
        float4 c1v = *(const float4*)Cp1;
        __syncthreads();   // all reads of previous c-tile's Cs / epilogue done
        *(float4*)&Cs[(0 * 128 + crow) * 20 + ckq]      = c0v;
        *(float4*)&Cs[(0 * 128 + crow + 64) * 20 + ckq] = c1v;
        __syncthreads();

        float acc[4][4][4] = {};

        for (int kt = 0; kt < 8; kt++) {
            const int cur = kt & 1, nxt = cur ^ 1;
            if (kt + 1 < 8) {
                c0v = *(const float4*)(Cp0 + (kt + 1) * 16);
                c1v = *(const float4*)(Cp1 + (kt + 1) * 16);
            }
            #pragma unroll
            for (int ks = 0; ks < 16; ks += 8) {
                const int kbase = kt * 16 + ks;
                unsigned ahi[4][4], alo[4][4];
                #pragma unroll
                for (int i = 0; i < 4; i++) {
                    const int r0 = (mw + i * 16 + g) * 132;
                    const int r1 = r0 + 8 * 132;
                    split_tf(Zs[r0 + kbase + tq],     ahi[i][0], alo[i][0]);
                    split_tf(Zs[r1 + kbase + tq],     ahi[i][1], alo[i][1]);
                    split_tf(Zs[r0 + kbase + tq + 4], ahi[i][2], alo[i][2]);
                    split_tf(Zs[r1 + kbase + tq + 4], ahi[i][3], alo[i][3]);
                }
                unsigned bhi[4][2], blo[4][2];
                #pragma unroll
                for (int j = 0; j < 4; j++) {
                    const int nc = (cur * 128 + nw + j * 8 + g) * 20 + ks;
                    split_tf(Cs[nc + tq],     bhi[j][0], blo[j][0]);
                    split_tf(Cs[nc + tq + 4], bhi[j][1], blo[j][1]);
                }
                #pragma unroll
                for (int i = 0; i < 4; i++)
                    #pragma unroll
                    for (int j = 0; j < 4; j++) {
                        mma8(acc[i][j], ahi[i][0], ahi[i][1], ahi[i][2], ahi[i][3], bhi[j][0], bhi[j][1]);
                        mma8(acc[i][j], ahi[i][0], ahi[i][1], ahi[i][2], ahi[i][3], blo[j][0], blo[j][1]);
                        mma8(acc[i][j], alo[i][0], alo[i][1], alo[i][2], alo[i][3], bhi[j][0], bhi[j][1]);
                    }
            }
            if (kt + 1 < 8) {
                *(float4*)&Cs[(nxt * 128 + crow) * 20 + ckq]      = c0v;
                *(float4*)&Cs[(nxt * 128 + crow + 64) * 20 + ckq] = c1v;
                __syncthreads();
            }
        }

        // argmin update: robust (d<bd)||(d==bd && c<bi) tie rule
        #pragma unroll
        for (int j = 0; j < 4; j++) {
            const int cbase = c0 + nw + j * 8 + tq * 2;
            const float cn0 = cn[cbase], cn1 = cn[cbase + 1];
            #pragma unroll
            for (int i = 0; i < 4; i++) {
                #pragma unroll
                for (int h = 0; h < 2; h++) {
                    const int s = i * 2 + h;
                    float d0 = fmaf(-2.0f, acc[i][j][h * 2 + 0], cn0);
                    float d1 = fmaf(-2.0f, acc[i][j][h * 2 + 1], cn1);
                    if (d0 < bestD[s] || (d0 == bestD[s] && cbase < bestI[s])) { bestD[s] = d0; bestI[s] = cbase; }
                    if (d1 < bestD[s] || (d1 == bestD[s] && cbase + 1 < bestI[s])) { bestD[s] = d1; bestI[s] = cbase + 1; }
                }
            }
        }
    }

    // reduce across the 4 lanes (tq) sharing each row
    #pragma unroll
    for (int s = 0; s < 8; s++) {
        #pragma unroll
        for (int o = 1; o < 4; o <<= 1) {
            float od = __shfl_xor_sync(0xFFFFFFFFu, bestD[s], o);
            int   oi = __shfl_xor_sync(0xFFFFFFFFu, bestI[s], o);
            if (od < bestD[s] || (od == bestD[s] && oi < bestI[s])) { bestD[s] = od; bestI[s] = oi; }
        }
    }
    if (tq == 0) {
        #pragma unroll
        for (int s = 0; s < 8; s++) {
            const int row = mw + (s >> 1) * 16 + (s & 1) * 8 + g;
            red_d[row][warpN] = bestD[s];
            red_i[row][warpN] = bestI[s];
        }
    }
    __syncthreads();
    if (tid < 128) {
        float bd = red_d[tid][0];
        int   bi = red_i[tid][0];
        #pragma unroll
        for (int x = 1; x < 4; x++) {
            float d = red_d[tid][x];
            int   c = red_i[tid][x];
            if (d < bd || (d == bd && c < bi)) { bd = d; bi = c; }
        }
        best_idx[tid] = bi;
        g_idx[t0 + tid] = bi;
    }
    __syncthreads();

    // gather + straight-through + commit loss (z from smem)
    float lsum = 0.f;
    float* qB = q + (size_t)t0 * EMBED;
    #pragma unroll 4
    for (int l = 0; l < 64; l++) {
        int e = l * 256 + tid;
        int trow = e >> 7;
        int d    = e & 127;
        int c    = best_idx[trow];
        float zv   = Zs[trow * 132 + d];
        float diff = cb[(size_t)c * EMBED + d] - zv;
        qB[e] = zv + diff;
        lsum = fmaf(diff, diff, lsum);
    }
    #pragma unroll
    for (int o = 16; o > 0; o >>= 1) lsum += __shfl_down_sync(0xFFFFFFFFu, lsum, o);
    if (lane == 0) warp_sum[warp] = lsum;
    __syncthreads();
    if (tid == 0) {
        float s = 0.f;
        #pragma unroll
        for (int w = 0; w < 8; w++) s += warp_sum[w];
        atomicAdd(&g_loss, (double)s);
    }
}

// ------------------------- tail outputs -------------------------
__global__ void finalize_kernel(float* __restrict__ out)
{
    int i = blockIdx.x * 256 + threadIdx.x;
    if (i < NTOKENS_TOTAL) out[REC_ELEMS + i] = (float)g_idx[i];
    if (i == 0) out[REC_ELEMS + NTOKENS_TOTAL] = (float)(g_loss / (double)QELEMS);
}

// ------------------------- launch -------------------------
#define VQ_SMEM ((128 * 132 + 2 * 128 * 20 + 1024) * 4)

extern "C" void kernel_launch(void* const* d_in, const int* in_sizes, int n_in,
                              void* d_out, int out_size)
{
    const float* x   = (const float*)d_in[0];
    const float* eW1 = (const float*)d_in[1];
    const float* eb1 = (const float*)d_in[2];
    const float* eW2 = (const float*)d_in[3];
    const float* eb2 = (const float*)d_in[4];
    const float* eW3 = (const float*)d_in[5];
    const float* eb3 = (const float*)d_in[6];
    const float* dW1 = (const float*)d_in[7];
    const float* db1 = (const float*)d_in[8];
    const float* dW2 = (const float*)d_in[9];
    const float* db2 = (const float*)d_in[10];
    const float* dW3 = (const float*)d_in[11];
    const float* db3 = (const float*)d_in[12];
    const float* cb  = (const float*)d_in[13];
    float* out = (float*)d_out;

    float *h1, *h2, *z, *q, *h3, *h4;
    cudaGetSymbolAddress((void**)&h1, g_h1);
    cudaGetSymbolAddress((void**)&h2, g_h2);
    cudaGetSymbolAddress((void**)&z,  g_z);
    cudaGetSymbolAddress((void**)&q,  g_q);
    cudaGetSymbolAddress((void**)&h3, g_h3);
    cudaGetSymbolAddress((void**)&h4, g_h4);

    cudaFuncSetAttribute(vq_kernel, cudaFuncAttributeMaxDynamicSharedMemorySize, VQ_SMEM);

    zero_loss_kernel<<<1, 1>>>();
    code_norm_kernel<<<4, 256>>>(cb);

    // encoder
    gemm_tc<1><<<dim3(HID / 128,    NB / 128), 256>>>(x,  eW1, eb1, h1, NB, IN_DIM, HID);
    gemm_tc<1><<<dim3(HID / 128,    NB / 128), 256>>>(h1, eW2, eb2, h2, NB, HID,    HID);
    gemm_tc<0><<<dim3(LATENT / 128, NB / 128), 256>>>(h2, eW3, eb3, z,  NB, HID,    LATENT);

    // VQ
    vq_kernel<<<NTOKENS_TOTAL / 128, 256, VQ_SMEM>>>(z, cb, q);

    // decoder
    gemm_tc<1><<<dim3(HID / 128,    NB / 128), 256>>>(q,  dW1, db1, h3, NB, LATENT, HID);
    gemm_tc<1><<<dim3(HID / 128,    NB / 128), 256>>>(h3, dW2, db2, h4, NB, HID,    HID);
    gemm_tc<0><<<dim3(IN_DIM / 128, NB / 128), 256>>>(h4, dW3, db3, out, NB, HID,   IN_DIM);

    if (out_size >= REC_ELEMS + NTOKENS_TOTAL + 1)
        finalize_kernel<<<(NTOKENS_TOTAL + 255) / 256, 256>>>(out);
}